// round 14
// baseline (speedup 1.0000x reference)
#include <cuda_runtime.h>
#include <cuda_bf16.h>
#include <cstdint>

#define SEQLEN 512
#define BATCH  64
#define INP    1024
#define HID    1024
#define G4     4096
#define NCTA   128

typedef unsigned long long ull;

// ---- device scratch (static) ----
__device__ float g_G[(size_t)SEQLEN * BATCH * G4];
__device__ __nv_bfloat16 g_Whi[(size_t)G4 * HID];   // permuted: [cta][gate*8+u][k]
__device__ __nv_bfloat16 g_Wlo[(size_t)G4 * HID];
__device__ __nv_bfloat16 g_hhi[2][BATCH * HID];     // ping-pong
__device__ __nv_bfloat16 g_hlo[2][BATCH * HID];
__device__ unsigned int g_flag[NCTA];               // per-CTA completed-step count

// ---- f32x2 helpers (fp32 input GEMM) ----
static __device__ __forceinline__ void ffma2(ull& a, ull x, ull y) {
    asm("fma.rn.f32x2 %0, %1, %2, %0;" : "+l"(a) : "l"(x), "l"(y));
}
static __device__ __forceinline__ ull pack2(float x, float y) {
    ull r; asm("mov.b64 %0, {%1, %2};" : "=l"(r) : "f"(x), "f"(y)); return r;
}
static __device__ __forceinline__ float2 unpack2(ull v) {
    float lo, hi; asm("mov.b64 {%0, %1}, %2;" : "=f"(lo), "=f"(hi) : "l"(v));
    return make_float2(lo, hi);
}

// ---- warp MMA primitives ----
static __device__ __forceinline__ uint32_t smem_u32(const void* p) {
    uint32_t a;
    asm("{ .reg .u64 t; cvta.to.shared.u64 t, %1; cvt.u32.u64 %0, t; }" : "=r"(a) : "l"(p));
    return a;
}
static __device__ __forceinline__ void ldsm4(uint32_t& r0, uint32_t& r1,
                                             uint32_t& r2, uint32_t& r3, uint32_t a) {
    asm volatile("ldmatrix.sync.aligned.m8n8.x4.shared.b16 {%0,%1,%2,%3}, [%4];"
                 : "=r"(r0), "=r"(r1), "=r"(r2), "=r"(r3) : "r"(a));
}
static __device__ __forceinline__ void mma16816(float* d, const uint32_t* a,
                                                uint32_t b0, uint32_t b1) {
    asm volatile("mma.sync.aligned.m16n8k16.row.col.f32.bf16.bf16.f32 "
                 "{%0,%1,%2,%3}, {%4,%5,%6,%7}, {%8,%9}, {%0,%1,%2,%3};"
                 : "+f"(d[0]), "+f"(d[1]), "+f"(d[2]), "+f"(d[3])
                 : "r"(a[0]), "r"(a[1]), "r"(a[2]), "r"(a[3]), "r"(b0), "r"(b1));
}
static __device__ __forceinline__ void cpa16(uint32_t dst, const void* src) {
    asm volatile("cp.async.cg.shared.global [%0], [%1], 16;" :: "r"(dst), "l"(src));
}
#define CP_COMMIT() asm volatile("cp.async.commit_group;" ::: "memory")
#define CP_WAIT1()  asm volatile("cp.async.wait_group 1;" ::: "memory")
#define CP_WAIT0()  asm volatile("cp.async.wait_group 0;" ::: "memory")
#define BAR1_256()  asm volatile("bar.sync 1, 256;" ::: "memory")

static __device__ __forceinline__ float sigf(float x) {
    return 1.0f / (1.0f + __expf(-x));
}
static __device__ __forceinline__ float tanhfast(float x) {
    return 2.0f / (1.0f + __expf(-2.0f * x)) - 1.0f;
}
static __device__ __forceinline__ unsigned ldacq_gpu(const unsigned* p) {
    unsigned v;
    asm volatile("ld.acquire.gpu.global.u32 %0, [%1];" : "=r"(v) : "l"(p) : "memory");
    return v;
}
static __device__ __forceinline__ void strel_sh(uint32_t a, unsigned v) {
    asm volatile("st.release.cta.shared.u32 [%0], %1;" :: "r"(a), "r"(v) : "memory");
}
static __device__ __forceinline__ unsigned ldacq_sh(uint32_t a) {
    unsigned v;
    asm volatile("ld.acquire.cta.shared.u32 %0, [%1];" : "=r"(v) : "r"(a) : "memory");
    return v;
}

// ---- init ----
__global__ void zero_state_kernel() {
    int i = blockIdx.x * blockDim.x + threadIdx.x;
    if (i < BATCH * HID) {
        g_hhi[0][i] = __float2bfloat16(0.0f);
        g_hlo[0][i] = __float2bfloat16(0.0f);
        g_hhi[1][i] = __float2bfloat16(0.0f);
        g_hlo[1][i] = __float2bfloat16(0.0f);
    }
    if (i < NCTA) g_flag[i] = 0u;
}

// ---- split + permute W_hh: cta = j>>3, local row = gate*8 + (j&7) ----
__global__ void wsplit_kernel(const float* __restrict__ Whh) {
    int idx = blockIdx.x * blockDim.x + threadIdx.x;
    if (idx >= G4 * HID) return;
    int gr = idx >> 10;
    int k  = idx & 1023;
    int gate = gr >> 10;
    int j    = gr & 1023;
    int cta  = j >> 3;
    int u    = j & 7;
    size_t dst = ((size_t)cta * 32 + gate * 8 + u) * 1024 + k;
    float w = Whh[(size_t)gr * 1024 + k];
    __nv_bfloat16 hi = __float2bfloat16(w);
    float res = w - __bfloat162float(hi);
    g_Whi[dst] = hi;
    g_Wlo[dst] = __float2bfloat16(res);
}

// ---- big input GEMM (proven): G = X @ W_ih^T + (b_ih + b_hh) ----
__global__ __launch_bounds__(256) void gemm_gates(
    const float* __restrict__ X, const float* __restrict__ Wih,
    const float* __restrict__ bih, const float* __restrict__ bhh)
{
    __shared__ __align__(16) float As[8][132];
    __shared__ __align__(16) float Bs[8][132];
    const int tid = threadIdx.x;
    const int bn = blockIdx.x, bm = blockIdx.y;
    const int lr = tid >> 1, lk = (tid & 1) << 2;
    const float* Ag = X   + (size_t)(bm * 128 + lr) * INP + lk;
    const float* Bg = Wih + (size_t)(bn * 128 + lr) * INP + lk;
    const int tx = tid & 15, ty = tid >> 4;

    ull acc[8][4];
    #pragma unroll
    for (int i = 0; i < 8; i++)
        #pragma unroll
        for (int j = 0; j < 4; j++) acc[i][j] = 0ull;

    for (int k0 = 0; k0 < INP; k0 += 8) {
        float4 av = *(const float4*)(Ag + k0);
        float4 bv = *(const float4*)(Bg + k0);
        __syncthreads();
        As[lk+0][lr] = av.x; As[lk+1][lr] = av.y; As[lk+2][lr] = av.z; As[lk+3][lr] = av.w;
        Bs[lk+0][lr] = bv.x; Bs[lk+1][lr] = bv.y; Bs[lk+2][lr] = bv.z; Bs[lk+3][lr] = bv.w;
        __syncthreads();
        #pragma unroll
        for (int kk = 0; kk < 8; kk++) {
            float4 a0 = *(const float4*)&As[kk][ty * 8];
            float4 a1 = *(const float4*)&As[kk][ty * 8 + 4];
            ulonglong2 b0 = *(const ulonglong2*)&Bs[kk][tx * 8];
            ulonglong2 b1 = *(const ulonglong2*)&Bs[kk][tx * 8 + 4];
            float a[8] = {a0.x,a0.y,a0.z,a0.w,a1.x,a1.y,a1.z,a1.w};
            #pragma unroll
            for (int i = 0; i < 8; i++) {
                ull aa = pack2(a[i], a[i]);
                ffma2(acc[i][0], aa, b0.x); ffma2(acc[i][1], aa, b0.y);
                ffma2(acc[i][2], aa, b1.x); ffma2(acc[i][3], aa, b1.y);
            }
        }
    }
    const int col0 = bn * 128 + tx * 8;
    float bias[8];
    #pragma unroll
    for (int j = 0; j < 8; j++) bias[j] = bih[col0 + j] + bhh[col0 + j];
    #pragma unroll
    for (int i = 0; i < 8; i++) {
        int row = bm * 128 + ty * 8 + i;
        float2 p0 = unpack2(acc[i][0]), p1 = unpack2(acc[i][1]);
        float2 p2 = unpack2(acc[i][2]), p3 = unpack2(acc[i][3]);
        float4 o0 = make_float4(p0.x+bias[0], p0.y+bias[1], p1.x+bias[2], p1.y+bias[3]);
        float4 o1 = make_float4(p2.x+bias[4], p2.y+bias[5], p3.x+bias[6], p3.y+bias[7]);
        *(float4*)&g_G[(size_t)row * G4 + col0    ] = o0;
        *(float4*)&g_G[(size_t)row * G4 + col0 + 4] = o1;
    }
}

// ---- smem layout (bytes) — identical to R10 ----
#define WSTRIDE   1032
#define SM_W      0
#define WHALF_SZ  (32 * WSTRIDE * 2)        // 66048
#define SM_H      (2 * WHALF_SZ)            // 132096
#define HSTRIDE   72
#define HB_SZ     (64 * HSTRIDE * 2)        // 9216
#define HBUF_SZ   (2 * HB_SZ)               // 18432
#define SM_GATES  (SM_H + 2 * HBUF_SZ)
#define SM_TOTAL  (SM_GATES + 32 * 68 * 4)  // 177664

static __device__ __forceinline__ void issue_chunk(
    int c, uint32_t hbuf, const char* hhi, const char* hlo, int tid)
{
    #pragma unroll
    for (int r = 0; r < 2; r++) {
        int i = tid + r * 256;
        int row = i >> 3, seg = i & 7;
        uint32_t d = hbuf + row * (HSTRIDE * 2) + seg * 16;
        cpa16(d,         hhi + (size_t)row * 2048 + c * 128 + seg * 16);
        cpa16(d + HB_SZ, hlo + (size_t)row * 2048 + c * 128 + seg * 16);
    }
}

// ---- persistent recurrence: R10 pipeline + poller-warp wavefront sync ----
// 288 threads: warps 0-7 compute (2M x 4N HMMA tiling), warp 8 = flag poller.
// Chunk c of step t gated on producer group c (CTAs 8c..8c+8) having flag >= t.
__global__ __launch_bounds__(288) void lstm_persist(
    const float* __restrict__ keep,
    const int*   __restrict__ training,
    float*       __restrict__ final_out)
{
    extern __shared__ __align__(16) char sm[];
    __shared__ unsigned int s_ready[16];
    const uint32_t smb  = smem_u32(sm);
    const uint32_t rdyb = smem_u32(s_ready);
    const int tid  = threadIdx.x;
    const int wid  = tid >> 5;
    const int lane = tid & 31;
    const int cta  = blockIdx.x;

    // load W slice into smem once (compute threads only)
    if (tid < 256) {
        const char* whi = (const char*)(g_Whi + (size_t)cta * 32 * 1024);
        const char* wlo = (const char*)(g_Wlo + (size_t)cta * 32 * 1024);
        for (int i = tid; i < 4096; i += 256) {
            int row = i >> 7, seg = i & 127;
            uint32_t off = row * (WSTRIDE * 2) + seg * 16;
            *(uint4*)(sm + SM_W + off)            = *(const uint4*)(whi + row * 2048 + seg * 16);
            *(uint4*)(sm + SM_W + WHALF_SZ + off) = *(const uint4*)(wlo + row * 2048 + seg * 16);
        }
    }
    if (tid < 16) s_ready[tid] = 0u;
    __syncthreads();   // all 288 — only full-CTA barrier; poller splits off after

    if (tid >= 256) {
        // ---- poller warp: global flags -> smem group minima, until all done ----
        const int l = lane;                 // 0..31, each covers flags[4l..4l+4)
        while (true) {
            unsigned m0 = ldacq_gpu(&g_flag[4 * l + 0]);
            unsigned m1 = ldacq_gpu(&g_flag[4 * l + 1]);
            unsigned m2 = ldacq_gpu(&g_flag[4 * l + 2]);
            unsigned m3 = ldacq_gpu(&g_flag[4 * l + 3]);
            unsigned m = min(min(m0, m1), min(m2, m3));
            unsigned o = __shfl_xor_sync(0xffffffffu, m, 1);
            unsigned gmin = min(m, o);
            if ((l & 1) == 0) strel_sh(rdyb + (l >> 1) * 4, gmin);
            if (__all_sync(0xffffffffu, gmin >= (unsigned)SEQLEN)) break;
        }
        return;
    }

    // ---- compute warps (tid < 256) ----
    const int   trn   = *training;
    const float scale = trn ? (1.0f / 0.9f) : 1.0f;

    const int wm = wid >> 2;
    const int wn = wid & 3;
    const int lr = lane & 7;
    const int g  = lane >> 3;
    const uint32_t aoff = smb + SM_W +
        (uint32_t)((wm * 16 + lr + ((g & 1) << 3)) * WSTRIDE + ((g >> 1) << 3)) * 2;
    const uint32_t boff =
        (uint32_t)((wn * 16 + lr + ((g >> 1) << 3)) * HSTRIDE + ((g & 1) << 3)) * 2;

    float* gates = (float*)(sm + SM_GATES);

    const int u  = tid >> 5;
    const int b2 = tid & 31;
    const int j  = cta * 8 + u;

    float creg[2] = {0.0f, 0.0f};

    #pragma unroll 1
    for (int t = 0; t < SEQLEN; t++) {
        const int rb = t & 1;
        const char* hhi = (const char*)g_hhi[rb];
        const char* hlo = (const char*)g_hlo[rb];
        const unsigned ut = (unsigned)t;

        // prefetch G + keep (overlaps the chunk-0 gate spin)
        float garr[8], karr[2];
        #pragma unroll
        for (int gg = 0; gg < 4; gg++)
            #pragma unroll
            for (int i = 0; i < 2; i++)
                garr[gg * 2 + i] =
                    __ldcg(&g_G[((size_t)t * BATCH + 2 * b2 + i) * G4 + gg * 1024 + j]);
        if (trn) {
            #pragma unroll
            for (int i = 0; i < 2; i++)
                karr[i] = __ldcg(&keep[((size_t)t * BATCH + 2 * b2 + i) * HID + j]);
        }

        while (ldacq_sh(rdyb + 0 * 4) < ut) {}
        issue_chunk(0, smb + SM_H, hhi, hlo, tid); CP_COMMIT();
        while (ldacq_sh(rdyb + 1 * 4) < ut) {}
        issue_chunk(1, smb + SM_H + HBUF_SZ, hhi, hlo, tid); CP_COMMIT();

        float acc0[4] = {0, 0, 0, 0}, acc1[4] = {0, 0, 0, 0};

        #pragma unroll 1
        for (int c = 0; c < 16; c++) {
            if (c < 15) { CP_WAIT1(); } else { CP_WAIT0(); }
            BAR1_256();

            const uint32_t hb = smb + SM_H + (c & 1) * HBUF_SZ;
            const uint32_t ac = aoff + c * 128;
            #pragma unroll
            for (int ks = 0; ks < 4; ks++) {
                const uint32_t kb = ks * 32;
                uint32_t ah[4], al[4], bh[4], bl[4];
                ldsm4(ah[0], ah[1], ah[2], ah[3], ac + kb);
                ldsm4(al[0], al[1], al[2], al[3], ac + WHALF_SZ + kb);
                ldsm4(bh[0], bh[1], bh[2], bh[3], hb + boff + kb);
                ldsm4(bl[0], bl[1], bl[2], bl[3], hb + boff + HB_SZ + kb);
                mma16816(acc0, ah, bh[0], bh[1]);
                mma16816(acc0, ah, bl[0], bl[1]);
                mma16816(acc0, al, bh[0], bh[1]);
                mma16816(acc1, ah, bh[2], bh[3]);
                mma16816(acc1, ah, bl[2], bl[3]);
                mma16816(acc1, al, bh[2], bh[3]);
            }
            BAR1_256();
            if (c + 2 < 16) {
                while (ldacq_sh(rdyb + (c + 2) * 4) < ut) {}
                issue_chunk(c + 2, hb, hhi, hlo, tid);
                CP_COMMIT();
            }
        }

        // D -> gates smem
        {
            const int r = lane >> 2, cb = (lane & 3) * 2;
            float* g0 = &gates[(wm * 16 + r) * 68 + wn * 16 + cb];
            float* g1 = &gates[(wm * 16 + r + 8) * 68 + wn * 16 + cb];
            g0[0] = acc0[0]; g0[1] = acc0[1];
            g1[0] = acc0[2]; g1[1] = acc0[3];
            g0[8] = acc1[0]; g0[9] = acc1[1];
            g1[8] = acc1[2]; g1[9] = acc1[3];
        }
        BAR1_256();

        // cell update; write h(t) into buffer rb^1
        __nv_bfloat16* whhi = g_hhi[rb ^ 1];
        __nv_bfloat16* whlo = g_hlo[rb ^ 1];
        #pragma unroll
        for (int i = 0; i < 2; i++) {
            const int b = 2 * b2 + i;
            float iv = gates[(0 * 8 + u) * 68 + b] + garr[0 * 2 + i];
            float fv = gates[(1 * 8 + u) * 68 + b] + garr[1 * 2 + i];
            float gv = gates[(2 * 8 + u) * 68 + b] + garr[2 * 2 + i];
            float ov = gates[(3 * 8 + u) * 68 + b] + garr[3 * 2 + i];
            float ig = sigf(iv);
            float fg = sigf(fv);
            float gg = tanhfast(gv);
            float og = sigf(ov);
            float cc = fg * creg[i] + ig * gg;
            creg[i] = cc;
            float h = og * tanhfast(cc);
            if (trn) h *= karr[i] * scale;
            __nv_bfloat16 hh = __float2bfloat16(h);
            float res = h - __bfloat162float(hh);
            __stcg(&whhi[b * HID + j], hh);
            __stcg(&whlo[b * HID + j], __float2bfloat16(res));
            if (t == SEQLEN - 1) final_out[b * HID + j] = h;
        }

        // publish: single cumulative fence by tid 0, then relaxed flag store
        BAR1_256();
        if (tid == 0) {
            __threadfence();
            unsigned nv = ut + 1u;
            asm volatile("st.relaxed.gpu.global.u32 [%0], %1;"
                         :: "l"(&g_flag[cta]), "r"(nv) : "memory");
        }
    }
}

extern "C" void kernel_launch(void* const* d_in, const int* in_sizes, int n_in,
                              void* d_out, int out_size) {
    const float* x    = (const float*)d_in[0];
    const float* keep = (const float*)d_in[1];
    const float* Wih  = (const float*)d_in[2];
    const float* Whh  = (const float*)d_in[3];
    const float* bih  = (const float*)d_in[4];
    const float* bhh  = (const float*)d_in[5];
    const int*   trn  = (const int*)d_in[6];
    float* out = (float*)d_out;

    cudaFuncSetAttribute(lstm_persist, cudaFuncAttributeMaxDynamicSharedMemorySize, SM_TOTAL);

    zero_state_kernel<<<256, 256>>>();
    wsplit_kernel<<<(G4 * HID + 255) / 256, 256>>>(Whh);
    dim3 g1(32, 256);
    gemm_gates<<<g1, 256>>>(x, Wih, bih, bhh);
    lstm_persist<<<NCTA, 288, SM_TOTAL>>>(keep, trn, out);
}

// round 15
// speedup vs baseline: 1.0562x; 1.0562x over previous
#include <cuda_runtime.h>
#include <cuda_bf16.h>
#include <cstdint>

#define SEQLEN 512
#define BATCH  64
#define INP    1024
#define HID    1024
#define G4     4096
#define NCTA   128

typedef unsigned long long ull;

// ---- device scratch (static) ----
__device__ float g_G[(size_t)SEQLEN * BATCH * G4];
__device__ __nv_bfloat16 g_Whi[(size_t)G4 * HID];        // permuted: [cta][gate*8+u][k]
__device__ __nv_bfloat16 g_Wlo[(size_t)G4 * HID];
__device__ __nv_bfloat16 g_hhi[2][2][32 * HID];          // [chain][pingpong][32 batches x k]
__device__ __nv_bfloat16 g_hlo[2][2][32 * HID];
__device__ unsigned int g_bar2[64];                      // [0]=chain A, [32]=chain B

// ---- f32x2 helpers (fp32 input GEMM) ----
static __device__ __forceinline__ void ffma2(ull& a, ull x, ull y) {
    asm("fma.rn.f32x2 %0, %1, %2, %0;" : "+l"(a) : "l"(x), "l"(y));
}
static __device__ __forceinline__ ull pack2(float x, float y) {
    ull r; asm("mov.b64 %0, {%1, %2};" : "=l"(r) : "f"(x), "f"(y)); return r;
}
static __device__ __forceinline__ float2 unpack2(ull v) {
    float lo, hi; asm("mov.b64 {%0, %1}, %2;" : "=f"(lo), "=f"(hi) : "l"(v));
    return make_float2(lo, hi);
}

// ---- warp MMA primitives ----
static __device__ __forceinline__ uint32_t smem_u32(const void* p) {
    uint32_t a;
    asm("{ .reg .u64 t; cvta.to.shared.u64 t, %1; cvt.u32.u64 %0, t; }" : "=r"(a) : "l"(p));
    return a;
}
static __device__ __forceinline__ void ldsm4(uint32_t& r0, uint32_t& r1,
                                             uint32_t& r2, uint32_t& r3, uint32_t a) {
    asm volatile("ldmatrix.sync.aligned.m8n8.x4.shared.b16 {%0,%1,%2,%3}, [%4];"
                 : "=r"(r0), "=r"(r1), "=r"(r2), "=r"(r3) : "r"(a));
}
static __device__ __forceinline__ void ldsm2(uint32_t& r0, uint32_t& r1, uint32_t a) {
    asm volatile("ldmatrix.sync.aligned.m8n8.x2.shared.b16 {%0,%1}, [%2];"
                 : "=r"(r0), "=r"(r1) : "r"(a));
}
static __device__ __forceinline__ void mma16816(float* d, const uint32_t* a,
                                                uint32_t b0, uint32_t b1) {
    asm volatile("mma.sync.aligned.m16n8k16.row.col.f32.bf16.bf16.f32 "
                 "{%0,%1,%2,%3}, {%4,%5,%6,%7}, {%8,%9}, {%0,%1,%2,%3};"
                 : "+f"(d[0]), "+f"(d[1]), "+f"(d[2]), "+f"(d[3])
                 : "r"(a[0]), "r"(a[1]), "r"(a[2]), "r"(a[3]), "r"(b0), "r"(b1));
}
static __device__ __forceinline__ void cpa16(uint32_t dst, const void* src) {
    asm volatile("cp.async.cg.shared.global [%0], [%1], 16;" :: "r"(dst), "l"(src));
}
#define CP_COMMIT() asm volatile("cp.async.commit_group;" ::: "memory")
#define CP_WAIT1()  asm volatile("cp.async.wait_group 1;" ::: "memory")
#define CP_WAIT0()  asm volatile("cp.async.wait_group 0;" ::: "memory")

static __device__ __forceinline__ float sigf(float x) {
    return 1.0f / (1.0f + __expf(-x));
}
static __device__ __forceinline__ float tanhfast(float x) {
    return 2.0f / (1.0f + __expf(-2.0f * x)) - 1.0f;
}

// ---- init ----
__global__ void zero_state_kernel() {
    int i = blockIdx.x * blockDim.x + threadIdx.x;
    if (i < 2 * 2 * 32 * HID) {
        ((__nv_bfloat16*)g_hhi)[i] = __float2bfloat16(0.0f);
        ((__nv_bfloat16*)g_hlo)[i] = __float2bfloat16(0.0f);
    }
    if (i < 64) g_bar2[i] = 0u;
}

// ---- split + permute W_hh: cta = j>>3, local row = gate*8 + (j&7) ----
__global__ void wsplit_kernel(const float* __restrict__ Whh) {
    int idx = blockIdx.x * blockDim.x + threadIdx.x;
    if (idx >= G4 * HID) return;
    int gr = idx >> 10;
    int k  = idx & 1023;
    int gate = gr >> 10;
    int j    = gr & 1023;
    int cta  = j >> 3;
    int u    = j & 7;
    size_t dst = ((size_t)cta * 32 + gate * 8 + u) * 1024 + k;
    float w = Whh[(size_t)gr * 1024 + k];
    __nv_bfloat16 hi = __float2bfloat16(w);
    float res = w - __bfloat162float(hi);
    g_Whi[dst] = hi;
    g_Wlo[dst] = __float2bfloat16(res);
}

// ---- big input GEMM (proven): G = X @ W_ih^T + (b_ih + b_hh) ----
__global__ __launch_bounds__(256) void gemm_gates(
    const float* __restrict__ X, const float* __restrict__ Wih,
    const float* __restrict__ bih, const float* __restrict__ bhh)
{
    __shared__ __align__(16) float As[8][132];
    __shared__ __align__(16) float Bs[8][132];
    const int tid = threadIdx.x;
    const int bn = blockIdx.x, bm = blockIdx.y;
    const int lr = tid >> 1, lk = (tid & 1) << 2;
    const float* Ag = X   + (size_t)(bm * 128 + lr) * INP + lk;
    const float* Bg = Wih + (size_t)(bn * 128 + lr) * INP + lk;
    const int tx = tid & 15, ty = tid >> 4;

    ull acc[8][4];
    #pragma unroll
    for (int i = 0; i < 8; i++)
        #pragma unroll
        for (int j = 0; j < 4; j++) acc[i][j] = 0ull;

    for (int k0 = 0; k0 < INP; k0 += 8) {
        float4 av = *(const float4*)(Ag + k0);
        float4 bv = *(const float4*)(Bg + k0);
        __syncthreads();
        As[lk+0][lr] = av.x; As[lk+1][lr] = av.y; As[lk+2][lr] = av.z; As[lk+3][lr] = av.w;
        Bs[lk+0][lr] = bv.x; Bs[lk+1][lr] = bv.y; Bs[lk+2][lr] = bv.z; Bs[lk+3][lr] = bv.w;
        __syncthreads();
        #pragma unroll
        for (int kk = 0; kk < 8; kk++) {
            float4 a0 = *(const float4*)&As[kk][ty * 8];
            float4 a1 = *(const float4*)&As[kk][ty * 8 + 4];
            ulonglong2 b0 = *(const ulonglong2*)&Bs[kk][tx * 8];
            ulonglong2 b1 = *(const ulonglong2*)&Bs[kk][tx * 8 + 4];
            float a[8] = {a0.x,a0.y,a0.z,a0.w,a1.x,a1.y,a1.z,a1.w};
            #pragma unroll
            for (int i = 0; i < 8; i++) {
                ull aa = pack2(a[i], a[i]);
                ffma2(acc[i][0], aa, b0.x); ffma2(acc[i][1], aa, b0.y);
                ffma2(acc[i][2], aa, b1.x); ffma2(acc[i][3], aa, b1.y);
            }
        }
    }
    const int col0 = bn * 128 + tx * 8;
    float bias[8];
    #pragma unroll
    for (int j = 0; j < 8; j++) bias[j] = bih[col0 + j] + bhh[col0 + j];
    #pragma unroll
    for (int i = 0; i < 8; i++) {
        int row = bm * 128 + ty * 8 + i;
        float2 p0 = unpack2(acc[i][0]), p1 = unpack2(acc[i][1]);
        float2 p2 = unpack2(acc[i][2]), p3 = unpack2(acc[i][3]);
        float4 o0 = make_float4(p0.x+bias[0], p0.y+bias[1], p1.x+bias[2], p1.y+bias[3]);
        float4 o1 = make_float4(p2.x+bias[4], p2.y+bias[5], p3.x+bias[6], p3.y+bias[7]);
        *(float4*)&g_G[(size_t)row * G4 + col0    ] = o0;
        *(float4*)&g_G[(size_t)row * G4 + col0 + 4] = o1;
    }
}

// ---- smem layout (bytes) ----
#define WSTRIDE   1032
#define SM_W      0
#define WHALF_SZ  (32 * WSTRIDE * 2)        // 66048
#define SM_H      (2 * WHALF_SZ)            // 132096
#define HSTRIDE   72                        // halves per h row (pad 8)
#define HB_SZ     (32 * HSTRIDE * 2)        // 4608 per (hi/lo), 32 rows
#define HBUF_SZ   (2 * HB_SZ)               // 9216
#define SM_GATES  (SM_H + 2 * HBUF_SZ)      // 150528: float[32][36]
#define SM_TOTAL  (SM_GATES + 32 * 36 * 4)  // 155136

// one 64-k chunk of one chain's h: 32 rows x 8 x 16B per half; 1 thread = 1 seg
static __device__ __forceinline__ void issue_chunk(
    int c, uint32_t hbuf, const char* hhi, const char* hlo, int tid)
{
    int row = tid >> 3, seg = tid & 7;
    uint32_t d = hbuf + row * (HSTRIDE * 2) + seg * 16;
    cpa16(d,         hhi + (size_t)row * 2048 + c * 128 + seg * 16);
    cpa16(d + HB_SZ, hlo + (size_t)row * 2048 + c * 128 + seg * 16);
}

// ---- persistent recurrence: two interleaved batch-chains (A=b0-31, B=b32-63) ----
// 128 CTAs x 256 thr (8 warps = 2M x 4N, n8 per warp). CTA: 32 D-rows, N=32, K=1024.
// Phase(ch,t) hides chain ch's barrier/exchange latency under the other chain's compute.
__global__ __launch_bounds__(256) void lstm_persist(
    const float* __restrict__ keep,
    const int*   __restrict__ training,
    float*       __restrict__ final_out)
{
    extern __shared__ __align__(16) char sm[];
    const uint32_t smb = smem_u32(sm);
    const int tid  = threadIdx.x;
    const int wid  = tid >> 5;
    const int lane = tid & 31;
    const int cta  = blockIdx.x;

    // load W slice into smem once
    {
        const char* whi = (const char*)(g_Whi + (size_t)cta * 32 * 1024);
        const char* wlo = (const char*)(g_Wlo + (size_t)cta * 32 * 1024);
        for (int i = tid; i < 4096; i += 256) {
            int row = i >> 7, seg = i & 127;
            uint32_t off = row * (WSTRIDE * 2) + seg * 16;
            *(uint4*)(sm + SM_W + off)            = *(const uint4*)(whi + row * 2048 + seg * 16);
            *(uint4*)(sm + SM_W + WHALF_SZ + off) = *(const uint4*)(wlo + row * 2048 + seg * 16);
        }
    }
    __syncthreads();

    const int   trn   = *training;
    const float scale = trn ? (1.0f / 0.9f) : 1.0f;

    // MMA tiling: 2M x 4N, each warp m16 x n8
    const int wm = wid >> 2;
    const int wn = wid & 3;
    const int lr = lane & 7;
    const int g  = lane >> 3;
    const uint32_t aoff = smb + SM_W +
        (uint32_t)((wm * 16 + lr + ((g & 1) << 3)) * WSTRIDE + ((g >> 1) << 3)) * 2;
    // B (x2): lanes 0-7 -> {n row, k0-7}, lanes 8-15 -> {n row, k8-15}
    const uint32_t boff =
        (uint32_t)((wn * 8 + (lane & 7)) * HSTRIDE) * 2 + (((lane >> 3) & 1) << 4);

    float* gates = (float*)(sm + SM_GATES);

    // cell mapping: unit u, one batch b2 per thread per chain
    const int u  = tid >> 5;
    const int b2 = tid & 31;
    const int j  = cta * 8 + u;

    float creg[2] = {0.0f, 0.0f};

    #pragma unroll 1
    for (int t = 0; t < SEQLEN; t++) {
        #pragma unroll
        for (int ch = 0; ch < 2; ch++) {
            const int rb = t & 1;
            const char* hhi = (const char*)g_hhi[ch][rb];
            const char* hlo = (const char*)g_hlo[ch][rb];
            const int bg = ch * 32 + b2;            // global batch

            // prefetch G + keep (independent of h; overlaps wait)
            float garr[4], karr;
            #pragma unroll
            for (int gg = 0; gg < 4; gg++)
                garr[gg] = __ldcg(&g_G[((size_t)t * BATCH + bg) * G4 + gg * 1024 + j]);
            karr = trn ? __ldcg(&keep[((size_t)t * BATCH + bg) * HID + j]) : 1.0f;

            // chain barrier: h_ch(t-1) complete everywhere (usually already true —
            // the other chain's phase ran in between)
            if (t > 0) {
                if (tid == 0) {
                    const unsigned int target = (unsigned int)NCTA * (unsigned int)t;
                    unsigned int v;
                    do {
                        asm volatile("ld.acquire.gpu.global.u32 %0, [%1];"
                                     : "=r"(v) : "l"(&g_bar2[ch * 32]) : "memory");
                    } while (v < target);
                }
                __syncthreads();
            }

            issue_chunk(0, smb + SM_H, hhi, hlo, tid); CP_COMMIT();
            issue_chunk(1, smb + SM_H + HBUF_SZ, hhi, hlo, tid); CP_COMMIT();

            float acc[4] = {0, 0, 0, 0};

            #pragma unroll 1
            for (int c = 0; c < 16; c++) {
                if (c < 15) { CP_WAIT1(); } else { CP_WAIT0(); }
                __syncthreads();

                const uint32_t hb = smb + SM_H + (c & 1) * HBUF_SZ;
                const uint32_t ac = aoff + c * 128;
                #pragma unroll
                for (int ks = 0; ks < 4; ks++) {
                    const uint32_t kb = ks * 32;
                    uint32_t ah[4], al[4], bh[2], bl[2];
                    ldsm4(ah[0], ah[1], ah[2], ah[3], ac + kb);
                    ldsm4(al[0], al[1], al[2], al[3], ac + WHALF_SZ + kb);
                    ldsm2(bh[0], bh[1], hb + boff + kb);
                    ldsm2(bl[0], bl[1], hb + boff + HB_SZ + kb);
                    mma16816(acc, ah, bh[0], bh[1]);
                    mma16816(acc, ah, bl[0], bl[1]);
                    mma16816(acc, al, bh[0], bh[1]);
                }
                __syncthreads();
                if (c + 2 < 16) { issue_chunk(c + 2, hb, hhi, hlo, tid); CP_COMMIT(); }
            }

            // D -> gates smem (32 rows x 32 batch, stride 36)
            {
                const int r = lane >> 2, cb = (lane & 3) * 2;
                float* g0 = &gates[(wm * 16 + r) * 36 + wn * 8 + cb];
                float* g1 = &gates[(wm * 16 + r + 8) * 36 + wn * 8 + cb];
                g0[0] = acc[0]; g0[1] = acc[1];
                g1[0] = acc[2]; g1[1] = acc[3];
            }
            __syncthreads();

            // cell update (1 batch/thread); write h into buffer rb^1 of this chain
            {
                __nv_bfloat16* whhi = g_hhi[ch][rb ^ 1];
                __nv_bfloat16* whlo = g_hlo[ch][rb ^ 1];
                float iv = gates[(0 * 8 + u) * 36 + b2] + garr[0];
                float fv = gates[(1 * 8 + u) * 36 + b2] + garr[1];
                float gv = gates[(2 * 8 + u) * 36 + b2] + garr[2];
                float ov = gates[(3 * 8 + u) * 36 + b2] + garr[3];
                float ig = sigf(iv);
                float fg = sigf(fv);
                float gg = tanhfast(gv);
                float og = sigf(ov);
                float cc = fg * creg[ch] + ig * gg;
                creg[ch] = cc;
                float h = og * tanhfast(cc);
                if (trn) h *= karr * scale;
                __nv_bfloat16 hh = __float2bfloat16(h);
                float res = h - __bfloat162float(hh);
                __stcg(&whhi[b2 * HID + j], hh);
                __stcg(&whlo[b2 * HID + j], __float2bfloat16(res));
                if (t == SEQLEN - 1) final_out[bg * HID + j] = h;
            }

            // publish: writes visible, then bump this chain's counter
            __syncthreads();
            if (tid == 0) {
                __threadfence();
                atomicAdd(&g_bar2[ch * 32], 1u);
            }
        }
    }
}

extern "C" void kernel_launch(void* const* d_in, const int* in_sizes, int n_in,
                              void* d_out, int out_size) {
    const float* x    = (const float*)d_in[0];
    const float* keep = (const float*)d_in[1];
    const float* Wih  = (const float*)d_in[2];
    const float* Whh  = (const float*)d_in[3];
    const float* bih  = (const float*)d_in[4];
    const float* bhh  = (const float*)d_in[5];
    const int*   trn  = (const int*)d_in[6];
    float* out = (float*)d_out;

    cudaFuncSetAttribute(lstm_persist, cudaFuncAttributeMaxDynamicSharedMemorySize, SM_TOTAL);

    zero_state_kernel<<<512, 256>>>();
    wsplit_kernel<<<(G4 * HID + 255) / 256, 256>>>(Whh);
    dim3 g1(32, 256);
    gemm_gates<<<g1, 256>>>(x, Wih, bih, bhh);
    lstm_persist<<<NCTA, 256, SM_TOTAL>>>(keep, trn, out);
}

// round 16
// speedup vs baseline: 1.1764x; 1.1138x over previous
#include <cuda_runtime.h>
#include <cuda_bf16.h>
#include <cstdint>

#define SEQLEN 512
#define BATCH  64
#define INP    1024
#define HID    1024
#define G4     4096
#define NCTA   128

typedef unsigned long long ull;

// ---- device scratch (static) ----
__device__ float g_G[(size_t)SEQLEN * BATCH * G4];
__device__ __nv_bfloat16 g_Whi[(size_t)G4 * HID];   // permuted: [cta][gate*8+u][k]
__device__ __nv_bfloat16 g_Wlo[(size_t)G4 * HID];
__device__ __nv_bfloat16 g_hhi[2][BATCH * HID];     // ping-pong
__device__ __nv_bfloat16 g_hlo[2][BATCH * HID];
__device__ unsigned int g_bar;

// ---- f32x2 helpers (fp32 input GEMM) ----
static __device__ __forceinline__ void ffma2(ull& a, ull x, ull y) {
    asm("fma.rn.f32x2 %0, %1, %2, %0;" : "+l"(a) : "l"(x), "l"(y));
}
static __device__ __forceinline__ ull pack2(float x, float y) {
    ull r; asm("mov.b64 %0, {%1, %2};" : "=l"(r) : "f"(x), "f"(y)); return r;
}
static __device__ __forceinline__ float2 unpack2(ull v) {
    float lo, hi; asm("mov.b64 {%0, %1}, %2;" : "=f"(lo), "=f"(hi) : "l"(v));
    return make_float2(lo, hi);
}

// ---- warp MMA primitives ----
static __device__ __forceinline__ uint32_t smem_u32(const void* p) {
    uint32_t a;
    asm("{ .reg .u64 t; cvta.to.shared.u64 t, %1; cvt.u32.u64 %0, t; }" : "=r"(a) : "l"(p));
    return a;
}
static __device__ __forceinline__ void ldsm4(uint32_t& r0, uint32_t& r1,
                                             uint32_t& r2, uint32_t& r3, uint32_t a) {
    asm volatile("ldmatrix.sync.aligned.m8n8.x4.shared.b16 {%0,%1,%2,%3}, [%4];"
                 : "=r"(r0), "=r"(r1), "=r"(r2), "=r"(r3) : "r"(a));
}
static __device__ __forceinline__ void mma16816(float* d, const uint32_t* a,
                                                uint32_t b0, uint32_t b1) {
    asm volatile("mma.sync.aligned.m16n8k16.row.col.f32.bf16.bf16.f32 "
                 "{%0,%1,%2,%3}, {%4,%5,%6,%7}, {%8,%9}, {%0,%1,%2,%3};"
                 : "+f"(d[0]), "+f"(d[1]), "+f"(d[2]), "+f"(d[3])
                 : "r"(a[0]), "r"(a[1]), "r"(a[2]), "r"(a[3]), "r"(b0), "r"(b1));
}
static __device__ __forceinline__ void cpa16(uint32_t dst, const void* src) {
    asm volatile("cp.async.cg.shared.global [%0], [%1], 16;" :: "r"(dst), "l"(src));
}
#define CP_COMMIT() asm volatile("cp.async.commit_group;" ::: "memory")
#define CP_WAIT1()  asm volatile("cp.async.wait_group 1;" ::: "memory")
#define CP_WAIT0()  asm volatile("cp.async.wait_group 0;" ::: "memory")

static __device__ __forceinline__ float sigf(float x) {
    return 1.0f / (1.0f + __expf(-x));
}
static __device__ __forceinline__ float tanhfast(float x) {
    return 2.0f / (1.0f + __expf(-2.0f * x)) - 1.0f;
}

// ---- init ----
__global__ void zero_state_kernel() {
    int i = blockIdx.x * blockDim.x + threadIdx.x;
    if (i < BATCH * HID) {
        g_hhi[0][i] = __float2bfloat16(0.0f);
        g_hlo[0][i] = __float2bfloat16(0.0f);
        g_hhi[1][i] = __float2bfloat16(0.0f);
        g_hlo[1][i] = __float2bfloat16(0.0f);
    }
    if (i == 0) g_bar = 0u;
}

// ---- split + permute W_hh: cta = j>>3, local row = gate*8 + (j&7) ----
__global__ void wsplit_kernel(const float* __restrict__ Whh) {
    int idx = blockIdx.x * blockDim.x + threadIdx.x;
    if (idx >= G4 * HID) return;
    int gr = idx >> 10;
    int k  = idx & 1023;
    int gate = gr >> 10;
    int j    = gr & 1023;
    int cta  = j >> 3;
    int u    = j & 7;
    size_t dst = ((size_t)cta * 32 + gate * 8 + u) * 1024 + k;
    float w = Whh[(size_t)gr * 1024 + k];
    __nv_bfloat16 hi = __float2bfloat16(w);
    float res = w - __bfloat162float(hi);
    g_Whi[dst] = hi;
    g_Wlo[dst] = __float2bfloat16(res);
}

// ---- big input GEMM (proven): G = X @ W_ih^T + (b_ih + b_hh) ----
__global__ __launch_bounds__(256) void gemm_gates(
    const float* __restrict__ X, const float* __restrict__ Wih,
    const float* __restrict__ bih, const float* __restrict__ bhh)
{
    __shared__ __align__(16) float As[8][132];
    __shared__ __align__(16) float Bs[8][132];
    const int tid = threadIdx.x;
    const int bn = blockIdx.x, bm = blockIdx.y;
    const int lr = tid >> 1, lk = (tid & 1) << 2;
    const float* Ag = X   + (size_t)(bm * 128 + lr) * INP + lk;
    const float* Bg = Wih + (size_t)(bn * 128 + lr) * INP + lk;
    const int tx = tid & 15, ty = tid >> 4;

    ull acc[8][4];
    #pragma unroll
    for (int i = 0; i < 8; i++)
        #pragma unroll
        for (int j = 0; j < 4; j++) acc[i][j] = 0ull;

    for (int k0 = 0; k0 < INP; k0 += 8) {
        float4 av = *(const float4*)(Ag + k0);
        float4 bv = *(const float4*)(Bg + k0);
        __syncthreads();
        As[lk+0][lr] = av.x; As[lk+1][lr] = av.y; As[lk+2][lr] = av.z; As[lk+3][lr] = av.w;
        Bs[lk+0][lr] = bv.x; Bs[lk+1][lr] = bv.y; Bs[lk+2][lr] = bv.z; Bs[lk+3][lr] = bv.w;
        __syncthreads();
        #pragma unroll
        for (int kk = 0; kk < 8; kk++) {
            float4 a0 = *(const float4*)&As[kk][ty * 8];
            float4 a1 = *(const float4*)&As[kk][ty * 8 + 4];
            ulonglong2 b0 = *(const ulonglong2*)&Bs[kk][tx * 8];
            ulonglong2 b1 = *(const ulonglong2*)&Bs[kk][tx * 8 + 4];
            float a[8] = {a0.x,a0.y,a0.z,a0.w,a1.x,a1.y,a1.z,a1.w};
            #pragma unroll
            for (int i = 0; i < 8; i++) {
                ull aa = pack2(a[i], a[i]);
                ffma2(acc[i][0], aa, b0.x); ffma2(acc[i][1], aa, b0.y);
                ffma2(acc[i][2], aa, b1.x); ffma2(acc[i][3], aa, b1.y);
            }
        }
    }
    const int col0 = bn * 128 + tx * 8;
    float bias[8];
    #pragma unroll
    for (int j = 0; j < 8; j++) bias[j] = bih[col0 + j] + bhh[col0 + j];
    #pragma unroll
    for (int i = 0; i < 8; i++) {
        int row = bm * 128 + ty * 8 + i;
        float2 p0 = unpack2(acc[i][0]), p1 = unpack2(acc[i][1]);
        float2 p2 = unpack2(acc[i][2]), p3 = unpack2(acc[i][3]);
        float4 o0 = make_float4(p0.x+bias[0], p0.y+bias[1], p1.x+bias[2], p1.y+bias[3]);
        float4 o1 = make_float4(p2.x+bias[4], p2.y+bias[5], p3.x+bias[6], p3.y+bias[7]);
        *(float4*)&g_G[(size_t)row * G4 + col0    ] = o0;
        *(float4*)&g_G[(size_t)row * G4 + col0 + 4] = o1;
    }
}

// ---- smem layout (bytes) ----
#define WSTRIDE   1032
#define SM_W      0
#define WHALF_SZ  (32 * WSTRIDE * 2)        // 66048
#define SM_H      (2 * WHALF_SZ)            // 132096
#define HSTRIDE   72
#define HB_SZ     (64 * HSTRIDE * 2)        // 9216
#define HBUF_SZ   (2 * HB_SZ)               // 18432
#define NBUF      3
#define SM_GATES  (SM_H + NBUF * HBUF_SZ)   // 187392: 2 x float[32][68]
#define GSZ       (32 * 68)
#define SM_TOTAL  (SM_GATES + 2 * GSZ * 4)  // 204800

static __device__ __forceinline__ void issue_chunk(
    int c, uint32_t hbuf, const char* hhi, const char* hlo, int tid)
{
    #pragma unroll
    for (int r = 0; r < 2; r++) {
        int i = tid + r * 256;
        int row = i >> 3, seg = i & 7;
        uint32_t d = hbuf + row * (HSTRIDE * 2) + seg * 16;
        cpa16(d,         hhi + (size_t)row * 2048 + c * 128 + seg * 16);
        cpa16(d + HB_SZ, hlo + (size_t)row * 2048 + c * 128 + seg * 16);
    }
}

// ---- persistent recurrence on HMMA tensor cores ----
// 128 CTAs x 256 thr. Warp tiling 2M x 2N x 2K: wm=wid>>2, wn=(wid>>1)&1, wk=wid&1.
// Each warp: m16 x n32 x (half the k-steps); wk partials summed in epilogue.
// NBUF=3 => single bar.sync per chunk; issue c+2 right after the bar.
__global__ __launch_bounds__(256) void lstm_persist(
    const float* __restrict__ keep,
    const int*   __restrict__ training,
    float*       __restrict__ final_out)
{
    extern __shared__ __align__(16) char sm[];
    const uint32_t smb = smem_u32(sm);
    const int tid  = threadIdx.x;
    const int wid  = tid >> 5;
    const int lane = tid & 31;
    const int cta  = blockIdx.x;

    // load W slice into smem once
    {
        const char* whi = (const char*)(g_Whi + (size_t)cta * 32 * 1024);
        const char* wlo = (const char*)(g_Wlo + (size_t)cta * 32 * 1024);
        for (int i = tid; i < 4096; i += 256) {
            int row = i >> 7, seg = i & 127;
            uint32_t off = row * (WSTRIDE * 2) + seg * 16;
            *(uint4*)(sm + SM_W + off)            = *(const uint4*)(whi + row * 2048 + seg * 16);
            *(uint4*)(sm + SM_W + WHALF_SZ + off) = *(const uint4*)(wlo + row * 2048 + seg * 16);
        }
    }
    __syncthreads();

    const int   trn   = *training;
    const float scale = trn ? (1.0f / 0.9f) : 1.0f;

    // MMA tiling: 2M x 2N x 2K
    const int wm = wid >> 2;            // 0..1: m16
    const int wn = (wid >> 1) & 1;      // 0..1: n32
    const int wk = wid & 1;             // 0..1: k-half of each chunk
    const int lr = lane & 7;
    const int g  = lane >> 3;
    const uint32_t aoff = smb + SM_W +
        (uint32_t)((wm * 16 + lr + ((g & 1) << 3)) * WSTRIDE + ((g >> 1) << 3)) * 2;
    uint32_t boff[2];
    #pragma unroll
    for (int q = 0; q < 2; q++)
        boff[q] = (uint32_t)((wn * 32 + q * 16 + lr + ((g >> 1) << 3)) * HSTRIDE
                             + ((g & 1) << 3)) * 2;

    float* gates = (float*)(sm + SM_GATES);    // [wk][32][68]

    // cell mapping
    const int u  = tid >> 5;
    const int b2 = tid & 31;
    const int j  = cta * 8 + u;

    float creg[2] = {0.0f, 0.0f};

    #pragma unroll 1
    for (int t = 0; t < SEQLEN; t++) {
        const int rb = t & 1;
        const char* hhi = (const char*)g_hhi[rb];
        const char* hlo = (const char*)g_hlo[rb];

        // prefetch G + keep (independent of h; overlaps barrier wait)
        float garr[8], karr[2];
        #pragma unroll
        for (int gg = 0; gg < 4; gg++)
            #pragma unroll
            for (int i = 0; i < 2; i++)
                garr[gg * 2 + i] =
                    __ldcg(&g_G[((size_t)t * BATCH + 2 * b2 + i) * G4 + gg * 1024 + j]);
        if (trn) {
            #pragma unroll
            for (int i = 0; i < 2; i++)
                karr[i] = __ldcg(&keep[((size_t)t * BATCH + 2 * b2 + i) * HID + j]);
        }

        // grid barrier: h(t-1) visible everywhere
        if (t > 0) {
            if (tid == 0) {
                const unsigned int target = (unsigned int)NCTA * (unsigned int)t;
                unsigned int v;
                do {
                    asm volatile("ld.acquire.gpu.global.u32 %0, [%1];"
                                 : "=r"(v) : "l"(&g_bar) : "memory");
                } while (v < target);
            }
            __syncthreads();
        }

        issue_chunk(0, smb + SM_H + 0 * HBUF_SZ, hhi, hlo, tid); CP_COMMIT();
        issue_chunk(1, smb + SM_H + 1 * HBUF_SZ, hhi, hlo, tid); CP_COMMIT();

        float acc[4][4];
        #pragma unroll
        for (int q = 0; q < 4; q++)
            #pragma unroll
            for (int i = 0; i < 4; i++) acc[q][i] = 0.0f;

        #pragma unroll 1
        for (int c = 0; c < 16; c++) {
            if (c < 15) { CP_WAIT1(); } else { CP_WAIT0(); }
            __syncthreads();    // all finished compute(c-1) => buffer (c+2)%3 free

            if (c + 2 < 16) {
                int nb = (c + 2) % NBUF;
                issue_chunk(c + 2, smb + SM_H + nb * HBUF_SZ, hhi, hlo, tid);
                CP_COMMIT();
            }

            const uint32_t hb = smb + SM_H + (c % NBUF) * HBUF_SZ;
            const uint32_t ac = aoff + c * 128;
            #pragma unroll
            for (int s = 0; s < 2; s++) {
                const uint32_t kb = (wk * 2 + s) * 32;
                uint32_t ah[4], al[4];
                ldsm4(ah[0], ah[1], ah[2], ah[3], ac + kb);
                ldsm4(al[0], al[1], al[2], al[3], ac + WHALF_SZ + kb);
                #pragma unroll
                for (int q = 0; q < 2; q++) {
                    uint32_t bh[4], bl[4];
                    ldsm4(bh[0], bh[1], bh[2], bh[3], hb + boff[q] + kb);
                    ldsm4(bl[0], bl[1], bl[2], bl[3], hb + boff[q] + HB_SZ + kb);
                    mma16816(acc[q * 2],     ah, bh[0], bh[1]);
                    mma16816(acc[q * 2],     ah, bl[0], bl[1]);
                    mma16816(acc[q * 2],     al, bh[0], bh[1]);
                    mma16816(acc[q * 2 + 1], ah, bh[2], bh[3]);
                    mma16816(acc[q * 2 + 1], ah, bl[2], bl[3]);
                    mma16816(acc[q * 2 + 1], al, bh[2], bh[3]);
                }
            }
        }
        __syncthreads();

        // D partials -> gates smem (wk 0/1 into disjoint arrays)
        {
            const int r = lane >> 2, cb = (lane & 3) * 2;
            float* gk = gates + wk * GSZ;
            #pragma unroll
            for (int q = 0; q < 4; q++) {
                const int col = wn * 32 + q * 8 + cb;
                float* g0 = &gk[(wm * 16 + r) * 68 + col];
                float* g1 = &gk[(wm * 16 + r + 8) * 68 + col];
                g0[0] = acc[q][0]; g0[1] = acc[q][1];
                g1[0] = acc[q][2]; g1[1] = acc[q][3];
            }
        }
        __syncthreads();

        // cell update; write h(t) into buffer rb^1
        __nv_bfloat16* whhi = g_hhi[rb ^ 1];
        __nv_bfloat16* whlo = g_hlo[rb ^ 1];
        #pragma unroll
        for (int i = 0; i < 2; i++) {
            const int b = 2 * b2 + i;
            float iv = gates[(0 * 8 + u) * 68 + b] + gates[GSZ + (0 * 8 + u) * 68 + b] + garr[0 * 2 + i];
            float fv = gates[(1 * 8 + u) * 68 + b] + gates[GSZ + (1 * 8 + u) * 68 + b] + garr[1 * 2 + i];
            float gv = gates[(2 * 8 + u) * 68 + b] + gates[GSZ + (2 * 8 + u) * 68 + b] + garr[2 * 2 + i];
            float ov = gates[(3 * 8 + u) * 68 + b] + gates[GSZ + (3 * 8 + u) * 68 + b] + garr[3 * 2 + i];
            float ig = sigf(iv);
            float fg = sigf(fv);
            float gg = tanhfast(gv);
            float og = sigf(ov);
            float cc = fg * creg[i] + ig * gg;
            creg[i] = cc;
            float h = og * tanhfast(cc);
            if (trn) h *= karr[i] * scale;
            __nv_bfloat16 hh = __float2bfloat16(h);
            float res = h - __bfloat162float(hh);
            __stcg(&whhi[b * HID + j], hh);
            __stcg(&whlo[b * HID + j], __float2bfloat16(res));
            if (t == SEQLEN - 1) final_out[b * HID + j] = h;
        }

        __threadfence();
        __syncthreads();
        if (tid == 0) atomicAdd(&g_bar, 1u);
    }
}

extern "C" void kernel_launch(void* const* d_in, const int* in_sizes, int n_in,
                              void* d_out, int out_size) {
    const float* x    = (const float*)d_in[0];
    const float* keep = (const float*)d_in[1];
    const float* Wih  = (const float*)d_in[2];
    const float* Whh  = (const float*)d_in[3];
    const float* bih  = (const float*)d_in[4];
    const float* bhh  = (const float*)d_in[5];
    const int*   trn  = (const int*)d_in[6];
    float* out = (float*)d_out;

    cudaFuncSetAttribute(lstm_persist, cudaFuncAttributeMaxDynamicSharedMemorySize, SM_TOTAL);

    zero_state_kernel<<<256, 256>>>();
    wsplit_kernel<<<(G4 * HID + 255) / 256, 256>>>(Whh);
    dim3 g1(32, 256);
    gemm_gates<<<g1, 256>>>(x, Wih, bih, bhh);
    lstm_persist<<<NCTA, 256, SM_TOTAL>>>(keep, trn, out);
}

// round 17
// speedup vs baseline: 1.1953x; 1.0160x over previous
#include <cuda_runtime.h>
#include <cuda_bf16.h>
#include <cstdint>

#define SEQLEN 512
#define BATCH  64
#define INP    1024
#define HID    1024
#define G4     4096
#define NCTA   128

typedef unsigned long long ull;

// ---- device scratch (static) ----
__device__ float g_G[(size_t)SEQLEN * BATCH * G4];
__device__ __nv_bfloat16 g_Whi[(size_t)G4 * HID];   // permuted: [cta][gate*8+u][k]
__device__ __nv_bfloat16 g_Wlo[(size_t)G4 * HID];
__device__ __nv_bfloat16 g_hhi[2][BATCH * HID];     // ping-pong
__device__ __nv_bfloat16 g_hlo[2][BATCH * HID];
__device__ unsigned int g_flag[NCTA];               // per-CTA completed-step count

// ---- f32x2 helpers (fp32 input GEMM) ----
static __device__ __forceinline__ void ffma2(ull& a, ull x, ull y) {
    asm("fma.rn.f32x2 %0, %1, %2, %0;" : "+l"(a) : "l"(x), "l"(y));
}
static __device__ __forceinline__ ull pack2(float x, float y) {
    ull r; asm("mov.b64 %0, {%1, %2};" : "=l"(r) : "f"(x), "f"(y)); return r;
}
static __device__ __forceinline__ float2 unpack2(ull v) {
    float lo, hi; asm("mov.b64 {%0, %1}, %2;" : "=f"(lo), "=f"(hi) : "l"(v));
    return make_float2(lo, hi);
}

// ---- warp MMA primitives ----
static __device__ __forceinline__ uint32_t smem_u32(const void* p) {
    uint32_t a;
    asm("{ .reg .u64 t; cvta.to.shared.u64 t, %1; cvt.u32.u64 %0, t; }" : "=r"(a) : "l"(p));
    return a;
}
static __device__ __forceinline__ void ldsm4(uint32_t& r0, uint32_t& r1,
                                             uint32_t& r2, uint32_t& r3, uint32_t a) {
    asm volatile("ldmatrix.sync.aligned.m8n8.x4.shared.b16 {%0,%1,%2,%3}, [%4];"
                 : "=r"(r0), "=r"(r1), "=r"(r2), "=r"(r3) : "r"(a));
}
static __device__ __forceinline__ void mma16816(float* d, const uint32_t* a,
                                                uint32_t b0, uint32_t b1) {
    asm volatile("mma.sync.aligned.m16n8k16.row.col.f32.bf16.bf16.f32 "
                 "{%0,%1,%2,%3}, {%4,%5,%6,%7}, {%8,%9}, {%0,%1,%2,%3};"
                 : "+f"(d[0]), "+f"(d[1]), "+f"(d[2]), "+f"(d[3])
                 : "r"(a[0]), "r"(a[1]), "r"(a[2]), "r"(a[3]), "r"(b0), "r"(b1));
}
static __device__ __forceinline__ void cpa16(uint32_t dst, const void* src) {
    asm volatile("cp.async.cg.shared.global [%0], [%1], 16;" :: "r"(dst), "l"(src));
}
#define CP_COMMIT() asm volatile("cp.async.commit_group;" ::: "memory")
#define CP_WAIT1()  asm volatile("cp.async.wait_group 1;" ::: "memory")
#define CP_WAIT0()  asm volatile("cp.async.wait_group 0;" ::: "memory")

static __device__ __forceinline__ float sigf(float x) {
    return 1.0f / (1.0f + __expf(-x));
}
static __device__ __forceinline__ float tanhfast(float x) {
    return 2.0f / (1.0f + __expf(-2.0f * x)) - 1.0f;
}
static __device__ __forceinline__ unsigned ldrelax(const unsigned* p) {
    unsigned v;
    asm volatile("ld.relaxed.gpu.global.u32 %0, [%1];" : "=r"(v) : "l"(p) : "memory");
    return v;
}

// ---- init ----
__global__ void zero_state_kernel() {
    int i = blockIdx.x * blockDim.x + threadIdx.x;
    if (i < BATCH * HID) {
        g_hhi[0][i] = __float2bfloat16(0.0f);
        g_hlo[0][i] = __float2bfloat16(0.0f);
        g_hhi[1][i] = __float2bfloat16(0.0f);
        g_hlo[1][i] = __float2bfloat16(0.0f);
    }
    if (i < NCTA) g_flag[i] = 0u;
}

// ---- split + permute W_hh: cta = j>>3, local row = gate*8 + (j&7) ----
__global__ void wsplit_kernel(const float* __restrict__ Whh) {
    int idx = blockIdx.x * blockDim.x + threadIdx.x;
    if (idx >= G4 * HID) return;
    int gr = idx >> 10;
    int k  = idx & 1023;
    int gate = gr >> 10;
    int j    = gr & 1023;
    int cta  = j >> 3;
    int u    = j & 7;
    size_t dst = ((size_t)cta * 32 + gate * 8 + u) * 1024 + k;
    float w = Whh[(size_t)gr * 1024 + k];
    __nv_bfloat16 hi = __float2bfloat16(w);
    float res = w - __bfloat162float(hi);
    g_Whi[dst] = hi;
    g_Wlo[dst] = __float2bfloat16(res);
}

// ---- big input GEMM (proven): G = X @ W_ih^T + (b_ih + b_hh) ----
__global__ __launch_bounds__(256) void gemm_gates(
    const float* __restrict__ X, const float* __restrict__ Wih,
    const float* __restrict__ bih, const float* __restrict__ bhh)
{
    __shared__ __align__(16) float As[8][132];
    __shared__ __align__(16) float Bs[8][132];
    const int tid = threadIdx.x;
    const int bn = blockIdx.x, bm = blockIdx.y;
    const int lr = tid >> 1, lk = (tid & 1) << 2;
    const float* Ag = X   + (size_t)(bm * 128 + lr) * INP + lk;
    const float* Bg = Wih + (size_t)(bn * 128 + lr) * INP + lk;
    const int tx = tid & 15, ty = tid >> 4;

    ull acc[8][4];
    #pragma unroll
    for (int i = 0; i < 8; i++)
        #pragma unroll
        for (int j = 0; j < 4; j++) acc[i][j] = 0ull;

    for (int k0 = 0; k0 < INP; k0 += 8) {
        float4 av = *(const float4*)(Ag + k0);
        float4 bv = *(const float4*)(Bg + k0);
        __syncthreads();
        As[lk+0][lr] = av.x; As[lk+1][lr] = av.y; As[lk+2][lr] = av.z; As[lk+3][lr] = av.w;
        Bs[lk+0][lr] = bv.x; Bs[lk+1][lr] = bv.y; Bs[lk+2][lr] = bv.z; Bs[lk+3][lr] = bv.w;
        __syncthreads();
        #pragma unroll
        for (int kk = 0; kk < 8; kk++) {
            float4 a0 = *(const float4*)&As[kk][ty * 8];
            float4 a1 = *(const float4*)&As[kk][ty * 8 + 4];
            ulonglong2 b0 = *(const ulonglong2*)&Bs[kk][tx * 8];
            ulonglong2 b1 = *(const ulonglong2*)&Bs[kk][tx * 8 + 4];
            float a[8] = {a0.x,a0.y,a0.z,a0.w,a1.x,a1.y,a1.z,a1.w};
            #pragma unroll
            for (int i = 0; i < 8; i++) {
                ull aa = pack2(a[i], a[i]);
                ffma2(acc[i][0], aa, b0.x); ffma2(acc[i][1], aa, b0.y);
                ffma2(acc[i][2], aa, b1.x); ffma2(acc[i][3], aa, b1.y);
            }
        }
    }
    const int col0 = bn * 128 + tx * 8;
    float bias[8];
    #pragma unroll
    for (int j = 0; j < 8; j++) bias[j] = bih[col0 + j] + bhh[col0 + j];
    #pragma unroll
    for (int i = 0; i < 8; i++) {
        int row = bm * 128 + ty * 8 + i;
        float2 p0 = unpack2(acc[i][0]), p1 = unpack2(acc[i][1]);
        float2 p2 = unpack2(acc[i][2]), p3 = unpack2(acc[i][3]);
        float4 o0 = make_float4(p0.x+bias[0], p0.y+bias[1], p1.x+bias[2], p1.y+bias[3]);
        float4 o1 = make_float4(p2.x+bias[4], p2.y+bias[5], p3.x+bias[6], p3.y+bias[7]);
        *(float4*)&g_G[(size_t)row * G4 + col0    ] = o0;
        *(float4*)&g_G[(size_t)row * G4 + col0 + 4] = o1;
    }
}

// ---- smem layout (bytes) — identical to R10 ----
#define WSTRIDE   1032
#define SM_W      0
#define WHALF_SZ  (32 * WSTRIDE * 2)        // 66048
#define SM_H      (2 * WHALF_SZ)            // 132096
#define HSTRIDE   72
#define HB_SZ     (64 * HSTRIDE * 2)        // 9216
#define HBUF_SZ   (2 * HB_SZ)               // 18432
#define SM_GATES  (SM_H + 2 * HBUF_SZ)
#define SM_TOTAL  (SM_GATES + 32 * 68 * 4)  // 177664

static __device__ __forceinline__ void issue_chunk(
    int c, uint32_t hbuf, const char* hhi, const char* hlo, int tid)
{
    #pragma unroll
    for (int r = 0; r < 2; r++) {
        int i = tid + r * 256;
        int row = i >> 3, seg = i & 7;
        uint32_t d = hbuf + row * (HSTRIDE * 2) + seg * 16;
        cpa16(d,         hhi + (size_t)row * 2048 + c * 128 + seg * 16);
        cpa16(d + HB_SZ, hlo + (size_t)row * 2048 + c * 128 + seg * 16);
    }
}

// ---- persistent recurrence on HMMA tensor cores (R10 schedule) ----
// 128 CTAs x 256 thr (8 warps = 2M x 4N). CTA: 32 D-rows (4 gates x 8 units), N=64, K=1024.
// Barrier: per-CTA flag store (no atomics) + warp-0 min-reduce detect with backoff.
__global__ __launch_bounds__(256) void lstm_persist(
    const float* __restrict__ keep,
    const int*   __restrict__ training,
    float*       __restrict__ final_out)
{
    extern __shared__ __align__(16) char sm[];
    const uint32_t smb = smem_u32(sm);
    const int tid  = threadIdx.x;
    const int wid  = tid >> 5;
    const int lane = tid & 31;
    const int cta  = blockIdx.x;

    // load W slice into smem once
    {
        const char* whi = (const char*)(g_Whi + (size_t)cta * 32 * 1024);
        const char* wlo = (const char*)(g_Wlo + (size_t)cta * 32 * 1024);
        for (int i = tid; i < 4096; i += 256) {
            int row = i >> 7, seg = i & 127;
            uint32_t off = row * (WSTRIDE * 2) + seg * 16;
            *(uint4*)(sm + SM_W + off)            = *(const uint4*)(whi + row * 2048 + seg * 16);
            *(uint4*)(sm + SM_W + WHALF_SZ + off) = *(const uint4*)(wlo + row * 2048 + seg * 16);
        }
    }
    __syncthreads();

    const int   trn   = *training;
    const float scale = trn ? (1.0f / 0.9f) : 1.0f;

    // MMA tiling (R10): 2M x 4N
    const int wm = wid >> 2;
    const int wn = wid & 3;
    const int lr = lane & 7;
    const int g  = lane >> 3;
    const uint32_t aoff = smb + SM_W +
        (uint32_t)((wm * 16 + lr + ((g & 1) << 3)) * WSTRIDE + ((g >> 1) << 3)) * 2;
    const uint32_t boff =
        (uint32_t)((wn * 16 + lr + ((g >> 1) << 3)) * HSTRIDE + ((g & 1) << 3)) * 2;

    float* gates = (float*)(sm + SM_GATES);

    // cell mapping
    const int u  = tid >> 5;
    const int b2 = tid & 31;
    const int j  = cta * 8 + u;

    float creg[2] = {0.0f, 0.0f};

    #pragma unroll 1
    for (int t = 0; t < SEQLEN; t++) {
        const int rb = t & 1;
        const char* hhi = (const char*)g_hhi[rb];
        const char* hlo = (const char*)g_hlo[rb];

        // prefetch G + keep (independent of h; overlaps barrier wait)
        float garr[8], karr[2];
        #pragma unroll
        for (int gg = 0; gg < 4; gg++)
            #pragma unroll
            for (int i = 0; i < 2; i++)
                garr[gg * 2 + i] =
                    __ldcg(&g_G[((size_t)t * BATCH + 2 * b2 + i) * G4 + gg * 1024 + j]);
        if (trn) {
            #pragma unroll
            for (int i = 0; i < 2; i++)
                karr[i] = __ldcg(&keep[((size_t)t * BATCH + 2 * b2 + i) * HID + j]);
        }

        // grid barrier detect: warp 0 min-reduces 128 flags with backoff
        if (t > 0) {
            if (tid < 32) {
                const unsigned ut = (unsigned)t;
                while (true) {
                    unsigned m0 = ldrelax(&g_flag[4 * lane + 0]);
                    unsigned m1 = ldrelax(&g_flag[4 * lane + 1]);
                    unsigned m2 = ldrelax(&g_flag[4 * lane + 2]);
                    unsigned m3 = ldrelax(&g_flag[4 * lane + 3]);
                    unsigned m = min(min(m0, m1), min(m2, m3));
                    if (__reduce_min_sync(0xffffffffu, m) >= ut) break;
                    __nanosleep(60);
                }
                asm volatile("fence.acq_rel.gpu;" ::: "memory");
            }
            __syncthreads();
        }

        issue_chunk(0, smb + SM_H, hhi, hlo, tid); CP_COMMIT();
        issue_chunk(1, smb + SM_H + HBUF_SZ, hhi, hlo, tid); CP_COMMIT();

        float acc0[4] = {0, 0, 0, 0}, acc1[4] = {0, 0, 0, 0};

        #pragma unroll 1
        for (int c = 0; c < 16; c++) {
            if (c < 15) { CP_WAIT1(); } else { CP_WAIT0(); }
            __syncthreads();

            const uint32_t hb = smb + SM_H + (c & 1) * HBUF_SZ;
            const uint32_t ac = aoff + c * 128;
            #pragma unroll
            for (int ks = 0; ks < 4; ks++) {
                const uint32_t kb = ks * 32;
                uint32_t ah[4], al[4], bh[4], bl[4];
                ldsm4(ah[0], ah[1], ah[2], ah[3], ac + kb);
                ldsm4(al[0], al[1], al[2], al[3], ac + WHALF_SZ + kb);
                ldsm4(bh[0], bh[1], bh[2], bh[3], hb + boff + kb);
                ldsm4(bl[0], bl[1], bl[2], bl[3], hb + boff + HB_SZ + kb);
                mma16816(acc0, ah, bh[0], bh[1]);
                mma16816(acc0, ah, bl[0], bl[1]);
                mma16816(acc0, al, bh[0], bh[1]);
                mma16816(acc1, ah, bh[2], bh[3]);
                mma16816(acc1, ah, bl[2], bl[3]);
                mma16816(acc1, al, bh[2], bh[3]);
            }
            __syncthreads();
            if (c + 2 < 16) { issue_chunk(c + 2, hb, hhi, hlo, tid); CP_COMMIT(); }
        }

        // D -> gates smem
        {
            const int r = lane >> 2, cb = (lane & 3) * 2;
            float* g0 = &gates[(wm * 16 + r) * 68 + wn * 16 + cb];
            float* g1 = &gates[(wm * 16 + r + 8) * 68 + wn * 16 + cb];
            g0[0] = acc0[0]; g0[1] = acc0[1];
            g1[0] = acc0[2]; g1[1] = acc0[3];
            g0[8] = acc1[0]; g0[9] = acc1[1];
            g1[8] = acc1[2]; g1[9] = acc1[3];
        }
        __syncthreads();

        // cell update; write h(t) into buffer rb^1
        __nv_bfloat16* whhi = g_hhi[rb ^ 1];
        __nv_bfloat16* whlo = g_hlo[rb ^ 1];
        #pragma unroll
        for (int i = 0; i < 2; i++) {
            const int b = 2 * b2 + i;
            float iv = gates[(0 * 8 + u) * 68 + b] + garr[0 * 2 + i];
            float fv = gates[(1 * 8 + u) * 68 + b] + garr[1 * 2 + i];
            float gv = gates[(2 * 8 + u) * 68 + b] + garr[2 * 2 + i];
            float ov = gates[(3 * 8 + u) * 68 + b] + garr[3 * 2 + i];
            float ig = sigf(iv);
            float fg = sigf(fv);
            float gg = tanhfast(gv);
            float og = sigf(ov);
            float cc = fg * creg[i] + ig * gg;
            creg[i] = cc;
            float h = og * tanhfast(cc);
            if (trn) h *= karr[i] * scale;
            __nv_bfloat16 hh = __float2bfloat16(h);
            float res = h - __bfloat162float(hh);
            __stcg(&whhi[b * HID + j], hh);
            __stcg(&whlo[b * HID + j], __float2bfloat16(res));
            if (t == SEQLEN - 1) final_out[b * HID + j] = h;
        }

        // arrive: single cumulative fence by tid 0, then relaxed flag store
        __syncthreads();
        if (tid == 0) {
            __threadfence();
            unsigned nv = (unsigned)t + 1u;
            asm volatile("st.relaxed.gpu.global.u32 [%0], %1;"
                         :: "l"(&g_flag[cta]), "r"(nv) : "memory");
        }
    }
}

extern "C" void kernel_launch(void* const* d_in, const int* in_sizes, int n_in,
                              void* d_out, int out_size) {
    const float* x    = (const float*)d_in[0];
    const float* keep = (const float*)d_in[1];
    const float* Wih  = (const float*)d_in[2];
    const float* Whh  = (const float*)d_in[3];
    const float* bih  = (const float*)d_in[4];
    const float* bhh  = (const float*)d_in[5];
    const int*   trn  = (const int*)d_in[6];
    float* out = (float*)d_out;

    cudaFuncSetAttribute(lstm_persist, cudaFuncAttributeMaxDynamicSharedMemorySize, SM_TOTAL);

    zero_state_kernel<<<256, 256>>>();
    wsplit_kernel<<<(G4 * HID + 255) / 256, 256>>>(Whh);
    dim3 g1(32, 256);
    gemm_gates<<<g1, 256>>>(x, Wih, bih, bhh);
    lstm_persist<<<NCTA, 256, SM_TOTAL>>>(keep, trn, out);
}